// round 3
// baseline (speedup 1.0000x reference)
#include <cuda_runtime.h>
#include <math.h>

#define NN 32768
#define EE 262144
#define FF 64
#define PSC 9
#define ZZ 10
#define NF (NN*FF)
#define NTILES (EE/128)
#define HS 68   // padded h row stride (floats)
#define BPZ 30  // blocks per species in node_pre

typedef unsigned long long u64;

// ---------------- device scratch ----------------
__device__ float g_skip_s[NF];
__device__ float g_skip_v[3*NF];
__device__ float g_sup[NF];
__device__ float g_vup[3*NF];
__device__ float g_agg_s[NF];
__device__ float g_agg_v[3*NF];
__device__ int g_cnt[ZZ];
__device__ int g_off[ZZ+1];
__device__ int g_cur[ZZ];
__device__ int g_list[NN];

// ---------------- f32x2 packed-math helpers ----------------
__device__ __forceinline__ u64 pack2(float x) {
    u64 r; asm("mov.b64 %0, {%1, %1};" : "=l"(r) : "f"(x)); return r;
}
__device__ __forceinline__ u64 fma2(u64 a, u64 b, u64 c) {
    u64 d; asm("fma.rn.f32x2 %0, %1, %2, %3;" : "=l"(d) : "l"(a), "l"(b), "l"(c)); return d;
}
__device__ __forceinline__ float2 unpk(u64 a) {
    float2 f; asm("mov.b64 {%0, %1}, %2;" : "=f"(f.x), "=f"(f.y) : "l"(a)); return f;
}
__device__ __forceinline__ float silu(float x) { return x / (1.f + __expf(-x)); }

// ---------------- setup kernels ----------------
__global__ void zero_agg() {
    int stride = gridDim.x * blockDim.x;
    int t = blockIdx.x * blockDim.x + threadIdx.x;
    for (int i = t; i < NF; i += stride) g_agg_s[i] = 0.f;
    for (int i = t; i < 3*NF; i += stride) g_agg_v[i] = 0.f;
    if (t < ZZ) g_cnt[t] = 0;
}
__global__ void count_species(const int* __restrict__ species) {
    int n = blockIdx.x * 256 + threadIdx.x;
    if (n < NN) atomicAdd(&g_cnt[species[n]], 1);
}
__global__ void scan_species() {
    if (threadIdx.x == 0 && blockIdx.x == 0) {
        int a = 0;
        for (int z = 0; z < ZZ; z++) { g_off[z] = a; g_cur[z] = a; a += g_cnt[z]; }
        g_off[ZZ] = a;
    }
}
__global__ void fill_species(const int* __restrict__ species) {
    int n = blockIdx.x * 256 + threadIdx.x;
    if (n < NN) {
        int p = atomicAdd(&g_cur[species[n]], 1);
        g_list[p] = n;
    }
}

// ---------------- kernel A: species-sorted skip linear + linear_up ----------------
// grid = ZZ*BPZ; block handles species z = blockIdx.x / BPZ
#define PRE_SMEM_FLOATS (4*4096 + 4*256)
__global__ void node_pre(const float* __restrict__ nf,
                         const float* __restrict__ Wss,
                         const float* __restrict__ Wsv,
                         const float* __restrict__ Wus,
                         const float* __restrict__ Wuv) {
    extern __shared__ float sm[];
    float* sWss = sm;
    float* sWsv = sm + 4096;
    float* sWus = sm + 8192;
    float* sWuv = sm + 12288;
    float* feat = sm + 16384;   // 4 groups * 256
    int z = blockIdx.x / BPZ, b = blockIdx.x % BPZ;
    int tid = threadIdx.x;
    const float* wssz = Wss + z * 4096;
    const float* wsvz = Wsv + z * 4096;
    for (int i = tid; i < 4096; i += 256) {
        sWss[i] = wssz[i]; sWsv[i] = wsvz[i]; sWus[i] = Wus[i]; sWuv[i] = Wuv[i];
    }
    __syncthreads();
    int g = tid & 63, grp = tid >> 6, bar = grp + 1;
    float* s_sh = feat + grp * 256;
    float* v_sh = s_sh + 64;
    int lo = g_off[z], hi = g_off[z+1];
    for (int idx = lo + b*4 + grp; idx < hi; idx += BPZ*4) {
        int n = g_list[idx];
        const float* row = nf + (size_t)n * 256;
        s_sh[g]       = row[g];
        v_sh[g]       = row[64 + g];
        v_sh[64 + g]  = row[128 + g];
        v_sh[128 + g] = row[192 + g];
        asm volatile("bar.sync %0, 64;" :: "r"(bar) : "memory");
        float ks = 0.f, kv0 = 0.f, kv1 = 0.f, kv2 = 0.f;
        float us = 0.f, uv0 = 0.f, uv1 = 0.f, uv2 = 0.f;
        #pragma unroll 8
        for (int f = 0; f < FF; f++) {
            float sv = s_sh[f];
            float a0 = v_sh[f*3], a1 = v_sh[f*3+1], a2 = v_sh[f*3+2];
            float w1 = sWss[f*64 + g];
            float w2 = sWsv[f*64 + g];
            float w3 = sWus[f*64 + g];
            float w4 = sWuv[f*64 + g];
            ks  += sv * w1; kv0 += a0 * w2; kv1 += a1 * w2; kv2 += a2 * w2;
            us  += sv * w3; uv0 += a0 * w4; uv1 += a1 * w4; uv2 += a2 * w4;
        }
        const float invZ = 0.039528471f;   // 1/sqrt(64*10)
        const float inv  = 0.125f;         // 1/sqrt(64)
        g_skip_s[n*64 + g]        = ks  * invZ;
        g_skip_v[0*NF + n*64 + g] = kv0 * invZ;
        g_skip_v[1*NF + n*64 + g] = kv1 * invZ;
        g_skip_v[2*NF + n*64 + g] = kv2 * invZ;
        g_sup[n*64 + g]           = us  * inv;
        g_vup[0*NF + n*64 + g]    = uv0 * inv;
        g_vup[1*NF + n*64 + g]    = uv1 * inv;
        g_vup[2*NF + n*64 + g]    = uv2 * inv;
        asm volatile("bar.sync %0, 64;" :: "r"(bar) : "memory");
    }
}

// ---------------- kernel B: fused radial MLP + TP + scatter ----------------
// smem floats: W1 512 | W2 4096 | W3 4096 | W4 20480 | RE 1024 | hA 8704 | hB 8704 |
//              sY 512 | sSn 128 | sRc 128  -> 48384 floats = 193536 B
#define MLP_SMEM_FLOATS (512 + 4096 + 4096 + 20480 + 1024 + 2*128*HS + 512 + 256)

__device__ __forceinline__ void epi_silu(u64 acc[4][4], float* h, int e0, int g0, float scale) {
    #pragma unroll
    for (int ee = 0; ee < 4; ee++) {
        float2 a = unpk(acc[0][ee]), b = unpk(acc[1][ee]);
        float2 c = unpk(acc[2][ee]), d = unpk(acc[3][ee]);
        float4 lo = make_float4(silu(a.x*scale), silu(a.y*scale), silu(b.x*scale), silu(b.y*scale));
        float4 hi = make_float4(silu(c.x*scale), silu(c.y*scale), silu(d.x*scale), silu(d.y*scale));
        *(float4*)(h + (e0+ee)*HS + g0)     = lo;
        *(float4*)(h + (e0+ee)*HS + g0 + 4) = hi;
    }
}

__device__ __forceinline__ void layer64(const float* __restrict__ hin,
                                        const float* __restrict__ W,
                                        float* hout, int e0, int g0) {
    u64 acc[4][4];
    #pragma unroll
    for (int gp = 0; gp < 4; gp++)
        #pragma unroll
        for (int ee = 0; ee < 4; ee++) acc[gp][ee] = 0ull;
    #pragma unroll 4
    for (int k = 0; k < 64; k++) {
        u64 hp[4];
        #pragma unroll
        for (int ee = 0; ee < 4; ee++) hp[ee] = pack2(hin[(e0+ee)*HS + k]);
        ulonglong2 wa = *(const ulonglong2*)(W + k*64 + g0);
        ulonglong2 wb = *(const ulonglong2*)(W + k*64 + g0 + 4);
        #pragma unroll
        for (int ee = 0; ee < 4; ee++) {
            acc[0][ee] = fma2(hp[ee], wa.x, acc[0][ee]);
            acc[1][ee] = fma2(hp[ee], wa.y, acc[1][ee]);
            acc[2][ee] = fma2(hp[ee], wb.x, acc[2][ee]);
            acc[3][ee] = fma2(hp[ee], wb.y, acc[3][ee]);
        }
    }
    epi_silu(acc, hout, e0, g0, 0.125f);
}

// one path's k-loop over hB with W4 slice at column offset 'poff'
__device__ __forceinline__ void path_pass(const float* __restrict__ hB,
                                          const float* __restrict__ sW4,
                                          int poff, int e0, int g0, u64 acc[4][4]) {
    #pragma unroll
    for (int gp = 0; gp < 4; gp++)
        #pragma unroll
        for (int ee = 0; ee < 4; ee++) acc[gp][ee] = 0ull;
    #pragma unroll 4
    for (int k = 0; k < 64; k++) {
        u64 hp[4];
        #pragma unroll
        for (int ee = 0; ee < 4; ee++) hp[ee] = pack2(hB[(e0+ee)*HS + k]);
        const float* wrow = sW4 + k*320 + poff + g0;
        ulonglong2 wa = *(const ulonglong2*)(wrow);
        ulonglong2 wb = *(const ulonglong2*)(wrow + 4);
        #pragma unroll
        for (int ee = 0; ee < 4; ee++) {
            acc[0][ee] = fma2(hp[ee], wa.x, acc[0][ee]);
            acc[1][ee] = fma2(hp[ee], wa.y, acc[1][ee]);
            acc[2][ee] = fma2(hp[ee], wb.x, acc[2][ee]);
            acc[3][ee] = fma2(hp[ee], wb.y, acc[3][ee]);
        }
    }
}

__device__ __forceinline__ void unpack8(u64 a[4][4], int ee, float* o) {
    #pragma unroll
    for (int gp = 0; gp < 4; gp++) {
        float2 t = unpk(a[gp][ee]);
        o[gp*2] = t.x; o[gp*2+1] = t.y;
    }
}

__global__ void mlp_tp_kernel(const float* __restrict__ re,
                              const float* __restrict__ vectors,
                              const float* __restrict__ W1,
                              const float* __restrict__ W2,
                              const float* __restrict__ W3,
                              const float* __restrict__ W4,
                              const int* __restrict__ senders,
                              const int* __restrict__ receivers) {
    extern __shared__ float sm[];
    float* sW1 = sm;
    float* sW2 = sW1 + 512;
    float* sW3 = sW2 + 4096;
    float* sW4 = sW3 + 4096;
    float* sRE = sW4 + 20480;
    float* hA  = sRE + 1024;
    float* hB  = hA + 128*HS;
    float* sY  = hB + 128*HS;      // [128][4]
    int*   sSn = (int*)(sY + 512);
    int*   sRc = sSn + 128;
    int tid = threadIdx.x;
    for (int i = tid; i < 512;   i += 256) sW1[i] = W1[i];
    for (int i = tid; i < 4096;  i += 256) { sW2[i] = W2[i]; sW3[i] = W3[i]; }
    for (int i = tid; i < 20480; i += 256) sW4[i] = W4[i];

    int e_base = blockIdx.x * 128;
    for (int i = tid; i < 1024; i += 256) sRE[i] = re[(size_t)e_base*8 + i];
    if (tid < 128) {
        int e = e_base + tid;
        float vx = __ldg(vectors + e*3), vy = __ldg(vectors + e*3 + 1), vz = __ldg(vectors + e*3 + 2);
        float rn = 1.f / (sqrtf(vx*vx + vy*vy + vz*vz) + 1e-9f);
        sY[tid*4]     = vx * rn;
        sY[tid*4 + 1] = vy * rn;
        sY[tid*4 + 2] = vz * rn;
        sSn[tid] = __ldg(senders + e);
        sRc[tid] = __ldg(receivers + e);
    }
    __syncthreads();

    int cj = tid & 7, ei = tid >> 3;
    int g0 = cj * 8, e0 = ei * 4;

    // layer 1: K=8
    {
        u64 acc[4][4];
        #pragma unroll
        for (int gp = 0; gp < 4; gp++)
            #pragma unroll
            for (int ee = 0; ee < 4; ee++) acc[gp][ee] = 0ull;
        #pragma unroll
        for (int k = 0; k < 8; k++) {
            u64 hp[4];
            #pragma unroll
            for (int ee = 0; ee < 4; ee++) hp[ee] = pack2(sRE[(e0+ee)*8 + k]);
            ulonglong2 wa = *(const ulonglong2*)(sW1 + k*64 + g0);
            ulonglong2 wb = *(const ulonglong2*)(sW1 + k*64 + g0 + 4);
            #pragma unroll
            for (int ee = 0; ee < 4; ee++) {
                acc[0][ee] = fma2(hp[ee], wa.x, acc[0][ee]);
                acc[1][ee] = fma2(hp[ee], wa.y, acc[1][ee]);
                acc[2][ee] = fma2(hp[ee], wb.x, acc[2][ee]);
                acc[3][ee] = fma2(hp[ee], wb.y, acc[3][ee]);
            }
        }
        epi_silu(acc, hB, e0, g0, 0.35355339f);   // 1/sqrt(8)
    }
    __syncthreads();
    layer64(hB, sW2, hA, e0, g0);   // layer 2
    __syncthreads();
    layer64(hA, sW3, hB, e0, g0);   // layer 3
    __syncthreads();                // hA free; hB = final hidden

    const float K1 = 0.03125f;       // 0.125 * EPS(0.25)
    const float K4 = 0.022097087f;   // 0.125 * 0.25 / sqrt(2)

    // ---- pass p4 -> store raw acc into hA (w4 buffer) ----
    {
        u64 acc4[4][4];
        path_pass(hB, sW4, 256, e0, g0, acc4);
        #pragma unroll
        for (int ee = 0; ee < 4; ee++) {
            float2 a = unpk(acc4[0][ee]), b = unpk(acc4[1][ee]);
            float2 c = unpk(acc4[2][ee]), d = unpk(acc4[3][ee]);
            *(float4*)(hA + (e0+ee)*HS + g0)     = make_float4(a.x, a.y, b.x, b.y);
            *(float4*)(hA + (e0+ee)*HS + g0 + 4) = make_float4(c.x, c.y, d.x, d.y);
        }
    }
    __syncthreads();

    // ---- pass p0 & p3 -> scalar scatter ----
    {
        u64 acc0[4][4], acc3[4][4];
        path_pass(hB, sW4, 0,   e0, g0, acc0);
        path_pass(hB, sW4, 192, e0, g0, acc3);
        #pragma unroll
        for (int ee = 0; ee < 4; ee++) {
            int le = e0 + ee;
            int sn = sSn[le], rc = sRc[le];
            float y0 = sY[le*4], y1 = sY[le*4+1], y2 = sY[le*4+2];
            float4 sl = *(const float4*)(g_sup + sn*64 + g0);
            float4 sh = *(const float4*)(g_sup + sn*64 + g0 + 4);
            float4 v0l = *(const float4*)(g_vup + 0*NF + sn*64 + g0);
            float4 v0h = *(const float4*)(g_vup + 0*NF + sn*64 + g0 + 4);
            float4 v1l = *(const float4*)(g_vup + 1*NF + sn*64 + g0);
            float4 v1h = *(const float4*)(g_vup + 1*NF + sn*64 + g0 + 4);
            float4 v2l = *(const float4*)(g_vup + 2*NF + sn*64 + g0);
            float4 v2h = *(const float4*)(g_vup + 2*NF + sn*64 + g0 + 4);
            float ssv[8] = {sl.x, sl.y, sl.z, sl.w, sh.x, sh.y, sh.z, sh.w};
            float b0v[8] = {v0l.x, v0l.y, v0l.z, v0l.w, v0h.x, v0h.y, v0h.z, v0h.w};
            float b1v[8] = {v1l.x, v1l.y, v1l.z, v1l.w, v1h.x, v1h.y, v1h.z, v1h.w};
            float b2v[8] = {v2l.x, v2l.y, v2l.z, v2l.w, v2h.x, v2h.y, v2h.z, v2h.w};
            float w0v[8], w3v[8];
            unpack8(acc0, ee, w0v);
            unpack8(acc3, ee, w3v);
            float* dst = g_agg_s + rc*64 + g0;
            #pragma unroll
            for (int j = 0; j < 8; j++) {
                float dot = b0v[j]*y0 + b1v[j]*y1 + b2v[j]*y2;
                atomicAdd(dst + j, K1 * (w0v[j]*ssv[j] + w3v[j]*dot));
            }
        }
    }

    // ---- pass p1 & p2 -> vector scatter (w4 from hA) ----
    {
        u64 acc1[4][4], acc2[4][4];
        path_pass(hB, sW4, 64,  e0, g0, acc1);
        path_pass(hB, sW4, 128, e0, g0, acc2);
        #pragma unroll
        for (int ee = 0; ee < 4; ee++) {
            int le = e0 + ee;
            int sn = sSn[le], rc = sRc[le];
            float y0 = sY[le*4], y1 = sY[le*4+1], y2 = sY[le*4+2];
            float4 v0l = *(const float4*)(g_vup + 0*NF + sn*64 + g0);
            float4 v0h = *(const float4*)(g_vup + 0*NF + sn*64 + g0 + 4);
            float4 v1l = *(const float4*)(g_vup + 1*NF + sn*64 + g0);
            float4 v1h = *(const float4*)(g_vup + 1*NF + sn*64 + g0 + 4);
            float4 v2l = *(const float4*)(g_vup + 2*NF + sn*64 + g0);
            float4 v2h = *(const float4*)(g_vup + 2*NF + sn*64 + g0 + 4);
            float4 w4l = *(const float4*)(hA + le*HS + g0);
            float4 w4h = *(const float4*)(hA + le*HS + g0 + 4);
            float b0v[8] = {v0l.x, v0l.y, v0l.z, v0l.w, v0h.x, v0h.y, v0h.z, v0h.w};
            float b1v[8] = {v1l.x, v1l.y, v1l.z, v1l.w, v1h.x, v1h.y, v1h.z, v1h.w};
            float b2v[8] = {v2l.x, v2l.y, v2l.z, v2l.w, v2h.x, v2h.y, v2h.z, v2h.w};
            float w4v[8] = {w4l.x, w4l.y, w4l.z, w4l.w, w4h.x, w4h.y, w4h.z, w4h.w};
            float w1v[8], w2v[8];
            unpack8(acc1, ee, w1v);
            unpack8(acc2, ee, w2v);
            float* d0 = g_agg_v + 0*NF + rc*64 + g0;
            float* d1 = g_agg_v + 1*NF + rc*64 + g0;
            float* d2 = g_agg_v + 2*NF + rc*64 + g0;
            #pragma unroll
            for (int j = 0; j < 8; j++) {
                float c0 = b1v[j]*y2 - b2v[j]*y1;
                float c1 = b2v[j]*y0 - b0v[j]*y2;
                float c2 = b0v[j]*y1 - b1v[j]*y0;
                atomicAdd(d0 + j, K1*(w1v[j]*y0 + w2v[j]*b0v[j]) + K4*w4v[j]*c0);
                atomicAdd(d1 + j, K1*(w1v[j]*y1 + w2v[j]*b1v[j]) + K4*w4v[j]*c1);
                atomicAdd(d2 + j, K1*(w1v[j]*y2 + w2v[j]*b2v[j]) + K4*w4v[j]*c2);
            }
        }
    }
}

// ---------------- kernel C: linear_down + symmetric contraction + post + skip + readout ----------------
#define POST_SMEM_FLOATS (4*4096 + 4*576)
__global__ void node_post(const float* __restrict__ Wds,
                          const float* __restrict__ Wdv,
                          const float* __restrict__ Wsc,
                          const float* __restrict__ Wps,
                          const float* __restrict__ Wpv,
                          const float* __restrict__ Wout,
                          const int*   __restrict__ species,
                          float* __restrict__ out) {
    extern __shared__ float sm[];
    float* sWds = sm;
    float* sWdv = sm + 4096;
    float* sWps = sm + 8192;
    float* sWpv = sm + 12288;
    float* buf  = sm + 16384;
    int tid = threadIdx.x;
    for (int i = tid; i < 4096; i += 256) {
        sWds[i] = Wds[i]; sWdv[i] = Wdv[i]; sWps[i] = Wps[i]; sWpv[i] = Wpv[i];
    }
    __syncthreads();
    int g = tid & 63, grp = tid >> 6, bar = grp + 1;
    float* ags = buf + grp * 576;
    float* agv = ags + 64;
    float* so  = agv + 192;
    float* vo  = so + 64;
    float* red = vo + 192;
    int group_id = blockIdx.x * 4 + grp;
    int totalGroups = gridDim.x * 4;
    for (int n = group_id; n < NN; n += totalGroups) {
        ags[g]       = g_agg_s[n*64 + g];
        agv[g]       = g_agg_v[0*NF + n*64 + g];
        agv[64 + g]  = g_agg_v[1*NF + n*64 + g];
        agv[128 + g] = g_agg_v[2*NF + n*64 + g];
        asm volatile("bar.sync %0, 64;" :: "r"(bar) : "memory");

        float sd = 0.f, vd0 = 0.f, vd1 = 0.f, vd2 = 0.f;
        #pragma unroll 8
        for (int f = 0; f < 64; f++) {
            float a  = ags[f];
            float a0 = agv[f], a1 = agv[64 + f], a2 = agv[128 + f];
            float w1 = sWds[f*64 + g], w2 = sWdv[f*64 + g];
            sd += a * w1; vd0 += a0 * w2; vd1 += a1 * w2; vd2 += a2 * w2;
        }
        sd *= 0.125f; vd0 *= 0.125f; vd1 *= 0.125f; vd2 *= 0.125f;

        int z = species[n];
        const float* wz = Wsc + z * (PSC*64) + g;
        float q0 = __ldg(wz),       q1 = __ldg(wz + 64),  q2 = __ldg(wz + 128);
        float q3 = __ldg(wz + 192), q4 = __ldg(wz + 256), q5 = __ldg(wz + 320);
        float q6 = __ldg(wz + 384), q7 = __ldg(wz + 448), q8 = __ldg(wz + 512);
        float vn2 = vd0*vd0 + vd1*vd1 + vd2*vd2;
        float s2  = sd * sd;
        float sout = q0*sd + q1*s2 + q2*vn2 + q3*s2*sd + q4*sd*vn2;
        float gv   = q5 + q6*sd + q7*s2 + q8*vn2;
        so[g] = sout;
        vo[g] = gv*vd0; vo[64 + g] = gv*vd1; vo[128 + g] = gv*vd2;
        asm volatile("bar.sync %0, 64;" :: "r"(bar) : "memory");

        float sp = 0.f, vp0 = 0.f, vp1 = 0.f, vp2 = 0.f;
        #pragma unroll 8
        for (int f = 0; f < 64; f++) {
            float a  = so[f];
            float a0 = vo[f], a1 = vo[64 + f], a2 = vo[128 + f];
            float w1 = sWps[f*64 + g], w2 = sWpv[f*64 + g];
            sp += a * w1; vp0 += a0 * w2; vp1 += a1 * w2; vp2 += a2 * w2;
        }
        sp  = sp  * 0.125f + g_skip_s[n*64 + g];
        vp0 = vp0 * 0.125f + g_skip_v[0*NF + n*64 + g];
        vp1 = vp1 * 0.125f + g_skip_v[1*NF + n*64 + g];
        vp2 = vp2 * 0.125f + g_skip_v[2*NF + n*64 + g];

        float* mrow = out + NN + (size_t)n * 256;
        mrow[g] = sp;
        mrow[64 + g*3]     = vp0;
        mrow[64 + g*3 + 1] = vp1;
        mrow[64 + g*3 + 2] = vp2;

        red[g] = sp * __ldg(Wout + g);
        asm volatile("bar.sync %0, 64;" :: "r"(bar) : "memory");
        if (g == 0) {
            float t2 = 0.f;
            #pragma unroll
            for (int i = 0; i < 64; i++) t2 += red[i];
            out[n] = t2 * 0.125f;
        }
        asm volatile("bar.sync %0, 64;" :: "r"(bar) : "memory");
    }
}

// ---------------- launch ----------------
extern "C" void kernel_launch(void* const* d_in, const int* in_sizes, int n_in,
                              void* d_out, int out_size) {
    const float* vectors    = (const float*)d_in[0];
    const float* node_feats = (const float*)d_in[1];
    const float* re         = (const float*)d_in[2];
    const float* Wss        = (const float*)d_in[3];
    const float* Wsv        = (const float*)d_in[4];
    const float* Wus        = (const float*)d_in[5];
    const float* Wuv        = (const float*)d_in[6];
    const float* W1         = (const float*)d_in[7];
    const float* W2         = (const float*)d_in[8];
    const float* W3         = (const float*)d_in[9];
    const float* W4         = (const float*)d_in[10];
    const float* Wds        = (const float*)d_in[11];
    const float* Wdv        = (const float*)d_in[12];
    const float* Wsc        = (const float*)d_in[13];
    const float* Wps        = (const float*)d_in[14];
    const float* Wpv        = (const float*)d_in[15];
    const float* Wout       = (const float*)d_in[16];
    const int*   species    = (const int*)d_in[17];
    const int*   senders    = (const int*)d_in[18];
    const int*   receivers  = (const int*)d_in[19];
    float* out = (float*)d_out;

    const int MLP_SMEM  = MLP_SMEM_FLOATS * 4;    // 193536 B
    const int PRE_SMEM  = PRE_SMEM_FLOATS * 4;    // 69632 B
    const int POST_SMEM = POST_SMEM_FLOATS * 4;   // 74752 B
    cudaFuncSetAttribute(mlp_tp_kernel, cudaFuncAttributeMaxDynamicSharedMemorySize, MLP_SMEM);
    cudaFuncSetAttribute(node_pre,      cudaFuncAttributeMaxDynamicSharedMemorySize, PRE_SMEM);
    cudaFuncSetAttribute(node_post,     cudaFuncAttributeMaxDynamicSharedMemorySize, POST_SMEM);

    zero_agg<<<2048, 256>>>();
    count_species<<<NN/256, 256>>>(species);
    scan_species<<<1, 32>>>();
    fill_species<<<NN/256, 256>>>(species);
    node_pre<<<ZZ*BPZ, 256, PRE_SMEM>>>(node_feats, Wss, Wsv, Wus, Wuv);
    mlp_tp_kernel<<<NTILES, 256, MLP_SMEM>>>(re, vectors, W1, W2, W3, W4, senders, receivers);
    node_post<<<444, 256, POST_SMEM>>>(Wds, Wdv, Wsc, Wps, Wpv, Wout, species, out);
}